// round 14
// baseline (speedup 1.0000x reference)
#include <cuda_runtime.h>
#include <cuda_bf16.h>
#include <cstdint>

// Problem shapes (fixed by the dataset)
#define S_LEN 2048
#define BATCH 16
#define DDIM  2048

// Stage-1 tiling: 4 o-rows x 16 b per thread; 8 LDS per 64 MACs.
#define OTILE   512                 // o rows per block (4 per thread)
#define KSPLIT  128
#define KCHUNK  (DDIM / KSPLIT)     // 16 d per block
#define WPAD    17                  // sW row stride: bank (o*17+d)%32, CF
#define SPAD    20                  // sS row stride (80B, 16B-aligned LDS.128)

// Scratch (device globals: allocation-free). g_part layout: [kc][o][b].
__device__ float g_part[KSPLIT * DDIM * BATCH];   // 16.8 MB
__device__ float g_altered[BATCH * DDIM];         // [b][o], 128 KB

__device__ __forceinline__ void ffma2(uint64_t& d, uint64_t a, uint64_t b) {
    asm("fma.rn.f32x2 %0, %1, %2, %0;" : "+l"(d) : "l"(a), "l"(b));
}

// ---------------------------------------------------------------------------
// Kernel 1a: partial[kc][o][b] = sum_{d in chunk kc} state[b][d] * W[o][d]
// Thread owns FOUR o rows (t, t+128, t+256, t+384) x all 16 b:
// per d: 4 scalar W LDS (stride-17 rows; 128*17%32==0 so all four reads hit
// the same conflict-free (t*17+d)%32 pattern) + 4 broadcast state LDS.128
// + 32 FFMA2  =>  8 LDS / 64 MACs -- 2.5x fewer shared-pipe instructions
// per MAC than the 12-13us variants (which sat at the LDS-count floor).
// Grid 512 = full single wave (~3.5 blocks/SM); launch_bounds caps regs.
// ---------------------------------------------------------------------------
__global__ void __launch_bounds__(128, 4)
stage1_part(const float* __restrict__ state,
            const float* __restrict__ W)
{
    __shared__ float sW[OTILE][WPAD];   // 512 x 17 x 4B = 34.8 KB
    __shared__ float sS[KCHUNK][SPAD];  // 1.25 KB

    const int t     = threadIdx.x;      // 0..127
    const int obase = blockIdx.x * OTILE;
    const int kc    = blockIdx.y;
    const int d0    = kc * KCHUNK;

    // --- Stage state chunk transposed: sS[d][b] (threads 0..63).
    if (t < 64) {
        const int b  = t >> 2;
        const int c4 = t & 3;
        const float4 v = *(const float4*)(state + b * DDIM + d0 + c4 * 4);
        sS[c4 * 4 + 0][b] = v.x;
        sS[c4 * 4 + 1][b] = v.y;
        sS[c4 * 4 + 2][b] = v.z;
        sS[c4 * 4 + 3][b] = v.w;
    }

    // --- Stage W tile 512 rows x 16 d: 2048 float4, 16/thread, coalesced
    // (4 f4 per row, 8 rows per warp -> nL=4). STS scalar: for fixed c4,k the
    // 8 distinct o rows map to distinct banks via stride 17.
#pragma unroll
    for (int j = 0; j < 16; ++j) {
        const int g  = j * 128 + t;
        const int r  = g >> 2;
        const int c4 = g & 3;
        const float4 v = *(const float4*)(W + (long)(obase + r) * DDIM + d0 + c4 * 4);
        sW[r][c4 * 4 + 0] = v.x;
        sW[r][c4 * 4 + 1] = v.y;
        sW[r][c4 * 4 + 2] = v.z;
        sW[r][c4 * 4 + 3] = v.w;
    }
    __syncthreads();

    uint64_t acc[4][8];                 // [o-row][b-pair] packed f32x2
#pragma unroll
    for (int i = 0; i < 4; ++i)
#pragma unroll
        for (int j = 0; j < 8; ++j) acc[i][j] = 0ull;

#pragma unroll
    for (int d = 0; d < KCHUNK; ++d) {
        uint64_t wp[4];
#pragma unroll
        for (int i = 0; i < 4; ++i) {
            const float w = sW[t + 128 * i][d];
            asm("mov.b64 %0, {%1, %1};" : "=l"(wp[i]) : "r"(__float_as_uint(w)));
        }
        const ulonglong2 q0 = *(const ulonglong2*)&sS[d][0];   // broadcast
        const ulonglong2 q1 = *(const ulonglong2*)&sS[d][4];
        const ulonglong2 q2 = *(const ulonglong2*)&sS[d][8];
        const ulonglong2 q3 = *(const ulonglong2*)&sS[d][12];
#pragma unroll
        for (int i = 0; i < 4; ++i) {
            ffma2(acc[i][0], wp[i], q0.x);  ffma2(acc[i][1], wp[i], q0.y);
            ffma2(acc[i][2], wp[i], q1.x);  ffma2(acc[i][3], wp[i], q1.y);
            ffma2(acc[i][4], wp[i], q2.x);  ffma2(acc[i][5], wp[i], q2.y);
            ffma2(acc[i][6], wp[i], q3.x);  ffma2(acc[i][7], wp[i], q3.y);
        }
    }

    // --- Store 4 partial rows: 16 consecutive floats each (4 STG.128).
#pragma unroll
    for (int i = 0; i < 4; ++i) {
        float res[16];
#pragma unroll
        for (int j = 0; j < 8; ++j)
            asm("mov.b64 {%0, %1}, %2;"
                : "=f"(res[2 * j]), "=f"(res[2 * j + 1]) : "l"(acc[i][j]));
        const int o = obase + t + 128 * i;
        float* dst = g_part + ((long)kc * DDIM + o) * BATCH;
#pragma unroll
        for (int q = 0; q < 4; ++q)
            *(float4*)(dst + q * 4) =
                make_float4(res[q * 4], res[q * 4 + 1], res[q * 4 + 2], res[q * 4 + 3]);
    }
}

// ---------------------------------------------------------------------------
// Kernel 1b: altered[b][o] = bias[o] + sum_kc partial[kc][o][b]
// 16.8 MB streamed, coalesced, deterministic fixed-order sum.
// ---------------------------------------------------------------------------
__global__ void __launch_bounds__(256)
stage1_reduce(const float* __restrict__ bias)
{
    const int n = blockIdx.x * 256 + threadIdx.x;   // 0..32767
    const int o = n >> 4;
    const int b = n & 15;
    float v = bias[o];
#pragma unroll 16
    for (int kc = 0; kc < KSPLIT; ++kc)
        v += g_part[(long)kc * DDIM * BATCH + n];
    g_altered[b * DDIM + o] = v;
}

// ---------------------------------------------------------------------------
// Kernel 2: weights[b][s] = sum_d altered[b][d] * enc[s][b][d]
// Streaming __ldcs loads; proven at the ~6.4 TB/s LTS chip cap.
// ---------------------------------------------------------------------------
__global__ void __launch_bounds__(256, 8)
stage2_dots(const float* __restrict__ enc,
            float* __restrict__ out)
{
    __shared__ float alt[DDIM];

    const int tid    = threadIdx.x;
    const int warpId = tid >> 5;
    const int lane   = tid & 31;
    const int b      = blockIdx.y;
    const int s      = blockIdx.x * 8 + warpId;

#pragma unroll
    for (int j = 0; j < 2; ++j) {
        int f4 = tid + j * 256;
        *(float4*)&alt[f4 * 4] = *(const float4*)(g_altered + b * DDIM + f4 * 4);
    }
    __syncthreads();

    const float4* row = (const float4*)(enc + ((long)s * BATCH + b) * DDIM);

    float4 acc = make_float4(0.f, 0.f, 0.f, 0.f);
#pragma unroll
    for (int i = 0; i < 16; ++i) {
        const int f4 = i * 32 + lane;
        const float4 e = __ldcs(row + f4);          // streaming load
        const float4 a = *(const float4*)&alt[f4 * 4];
        acc.x += e.x * a.x;
        acc.y += e.y * a.y;
        acc.z += e.z * a.z;
        acc.w += e.w * a.w;
    }

    float tt = (acc.x + acc.y) + (acc.z + acc.w);
#pragma unroll
    for (int off = 16; off > 0; off >>= 1)
        tt += __shfl_down_sync(0xFFFFFFFFu, tt, off);

    if (lane == 0)
        out[b * S_LEN + s] = tt;   // output shape [B, S]
}

extern "C" void kernel_launch(void* const* d_in, const int* in_sizes, int n_in,
                              void* d_out, int out_size)
{
    const float* enc   = (const float*)d_in[0];  // [S, B, D]
    const float* state = (const float*)d_in[1];  // [B, D]
    const float* W     = (const float*)d_in[2];  // [D, D]
    const float* bias  = (const float*)d_in[3];  // [D]
    float* out         = (float*)d_out;          // [B, S]

    stage1_part<<<dim3(DDIM / OTILE, KSPLIT), 128>>>(state, W);
    stage1_reduce<<<(BATCH * DDIM) / 256, 256>>>(bias);
    stage2_dots<<<dim3(S_LEN / 8, BATCH), 256>>>(enc, out);
}

// round 15
// speedup vs baseline: 1.0988x; 1.0988x over previous
#include <cuda_runtime.h>
#include <cuda_bf16.h>
#include <cstdint>

// Problem shapes (fixed by the dataset)
#define S_LEN 2048
#define BATCH 16
#define DDIM  2048

// Stage-1 tiling: O_t=2, B_t=16 per thread (R9 proven); 2 subtiles per block.
#define OTILE   256                 // o rows per block (2 per thread)
#define KSPLIT  32
#define KCHUNK  (DDIM / KSPLIT)     // 64 d per block, as 2 x 32-d subtiles
#define SUBK    32
#define NSUB    (KCHUNK / SUBK)     // 2
#define WPAD    33                  // sW bank = (r + d) % 32 -> conflict-free
#define SPAD    20                  // sS row stride (80B, 16B-aligned LDS.128)

// Scratch (device globals: allocation-free). g_part layout: [kc][o][b].
__device__ float g_part[KSPLIT * DDIM * BATCH];   // 4 MB
__device__ float g_altered[BATCH * DDIM];         // [b][o], 128 KB

__device__ __forceinline__ void ffma2(uint64_t& d, uint64_t a, uint64_t b) {
    asm("fma.rn.f32x2 %0, %1, %2, %0;" : "+l"(d) : "l"(a), "l"(b));
}

// ---------------------------------------------------------------------------
// Kernel 1a: partial[kc][o][b] = sum_{d in 64-chunk kc} state[b][d] * W[o][d]
// R9 inner loop (2 o-rows x 16 b per thread; per d: 2 scalar W LDS +
// 4 broadcast state LDS.128 + 16 FFMA2), run over two 32-d subtiles with
// accumulators carried across -> half the partial traffic of R9.
// ---------------------------------------------------------------------------
__global__ void __launch_bounds__(128)
stage1_part(const float* __restrict__ state,
            const float* __restrict__ W)
{
    __shared__ float sW[OTILE][WPAD];   // 33.8 KB (reloaded per subtile)
    __shared__ float sS[SUBK][SPAD];    // 2.5 KB

    const int t     = threadIdx.x;      // 0..127
    const int obase = blockIdx.x * OTILE;
    const int kc    = blockIdx.y;

    uint64_t acc0[8], acc1[8];          // 2 o-rows x 8 b-pairs (f32x2)
#pragma unroll
    for (int i = 0; i < 8; ++i) { acc0[i] = 0ull; acc1[i] = 0ull; }

#pragma unroll
    for (int sc = 0; sc < NSUB; ++sc) {
        const int d0 = kc * KCHUNK + sc * SUBK;

        // Stage state subtile transposed: sS[d][b]. Coalesced float4 LDG.
        {
            const int b  = t >> 3;
            const int c4 = t & 7;
            const float4 v = *(const float4*)(state + b * DDIM + d0 + c4 * 4);
            sS[c4 * 4 + 0][b] = v.x;
            sS[c4 * 4 + 1][b] = v.y;
            sS[c4 * 4 + 2][b] = v.z;
            sS[c4 * 4 + 3][b] = v.w;
        }

        // Stage W tile 256 rows x 32 d: 2048 float4, 16/thread, coalesced
        // (8 lanes/row -> nL=4); STS banks (r + 4c4 + k) % 32 conflict-free.
#pragma unroll
        for (int j = 0; j < 16; ++j) {
            const int g  = j * 128 + t;
            const int r  = g >> 3;
            const int c4 = g & 7;
            const float4 v = *(const float4*)(W + (long)(obase + r) * DDIM + d0 + c4 * 4);
            sW[r][c4 * 4 + 0] = v.x;
            sW[r][c4 * 4 + 1] = v.y;
            sW[r][c4 * 4 + 2] = v.z;
            sW[r][c4 * 4 + 3] = v.w;
        }
        __syncthreads();

#pragma unroll 8
        for (int d = 0; d < SUBK; ++d) {
            const float w0 = sW[t][d];             // bank (t+d)%32
            const float w1 = sW[t + 128][d];       // same pattern, CF
            uint64_t wp0, wp1;
            asm("mov.b64 %0, {%1, %1};" : "=l"(wp0) : "r"(__float_as_uint(w0)));
            asm("mov.b64 %0, {%1, %1};" : "=l"(wp1) : "r"(__float_as_uint(w1)));
            const ulonglong2 q0 = *(const ulonglong2*)&sS[d][0];   // broadcast
            const ulonglong2 q1 = *(const ulonglong2*)&sS[d][4];
            const ulonglong2 q2 = *(const ulonglong2*)&sS[d][8];
            const ulonglong2 q3 = *(const ulonglong2*)&sS[d][12];
            ffma2(acc0[0], wp0, q0.x);  ffma2(acc0[1], wp0, q0.y);
            ffma2(acc0[2], wp0, q1.x);  ffma2(acc0[3], wp0, q1.y);
            ffma2(acc0[4], wp0, q2.x);  ffma2(acc0[5], wp0, q2.y);
            ffma2(acc0[6], wp0, q3.x);  ffma2(acc0[7], wp0, q3.y);
            ffma2(acc1[0], wp1, q0.x);  ffma2(acc1[1], wp1, q0.y);
            ffma2(acc1[2], wp1, q1.x);  ffma2(acc1[3], wp1, q1.y);
            ffma2(acc1[4], wp1, q2.x);  ffma2(acc1[5], wp1, q2.y);
            ffma2(acc1[6], wp1, q3.x);  ffma2(acc1[7], wp1, q3.y);
        }
        __syncthreads();   // protect sW/sS before next subtile overwrite
    }

    // --- Store both partial rows: 16 consecutive floats each (4 STG.128).
#pragma unroll
    for (int half = 0; half < 2; ++half) {
        const uint64_t* a = half ? acc1 : acc0;
        float res[16];
#pragma unroll
        for (int j = 0; j < 8; ++j)
            asm("mov.b64 {%0, %1}, %2;"
                : "=f"(res[2 * j]), "=f"(res[2 * j + 1]) : "l"(a[j]));
        const int o = obase + t + 128 * half;
        float* dst = g_part + ((long)kc * DDIM + o) * BATCH;
#pragma unroll
        for (int q = 0; q < 4; ++q)
            *(float4*)(dst + q * 4) =
                make_float4(res[q * 4], res[q * 4 + 1], res[q * 4 + 2], res[q * 4 + 3]);
    }
}

// ---------------------------------------------------------------------------
// Kernel 1b: altered[b][o] = bias[o] + sum_kc partial[kc][o][b]
// 4 MB streamed via 32 independent __ldcg streams; fixed-order deterministic.
// ---------------------------------------------------------------------------
__global__ void __launch_bounds__(256)
stage1_reduce(const float* __restrict__ bias)
{
    const int n = blockIdx.x * 256 + threadIdx.x;   // 0..32767
    const int o = n >> 4;
    const int b = n & 15;
    float v = bias[o];
#pragma unroll
    for (int kc = 0; kc < KSPLIT; ++kc)
        v += __ldcg(&g_part[(long)kc * DDIM * BATCH + n]);
    g_altered[b * DDIM + o] = v;
}

// ---------------------------------------------------------------------------
// Kernel 2: weights[b][s] = sum_d altered[b][d] * enc[s][b][d]
// Streaming __ldcs loads; proven at the ~6.4 TB/s LTS chip cap (42.6us).
// ---------------------------------------------------------------------------
__global__ void __launch_bounds__(256, 8)
stage2_dots(const float* __restrict__ enc,
            float* __restrict__ out)
{
    __shared__ float alt[DDIM];

    const int tid    = threadIdx.x;
    const int warpId = tid >> 5;
    const int lane   = tid & 31;
    const int b      = blockIdx.y;
    const int s      = blockIdx.x * 8 + warpId;

#pragma unroll
    for (int j = 0; j < 2; ++j) {
        int f4 = tid + j * 256;
        *(float4*)&alt[f4 * 4] = *(const float4*)(g_altered + b * DDIM + f4 * 4);
    }
    __syncthreads();

    const float4* row = (const float4*)(enc + ((long)s * BATCH + b) * DDIM);

    float4 acc = make_float4(0.f, 0.f, 0.f, 0.f);
#pragma unroll
    for (int i = 0; i < 16; ++i) {
        const int f4 = i * 32 + lane;
        const float4 e = __ldcs(row + f4);          // streaming load
        const float4 a = *(const float4*)&alt[f4 * 4];
        acc.x += e.x * a.x;
        acc.y += e.y * a.y;
        acc.z += e.z * a.z;
        acc.w += e.w * a.w;
    }

    float tt = (acc.x + acc.y) + (acc.z + acc.w);
#pragma unroll
    for (int off = 16; off > 0; off >>= 1)
        tt += __shfl_down_sync(0xFFFFFFFFu, tt, off);

    if (lane == 0)
        out[b * S_LEN + s] = tt;   // output shape [B, S]
}

extern "C" void kernel_launch(void* const* d_in, const int* in_sizes, int n_in,
                              void* d_out, int out_size)
{
    const float* enc   = (const float*)d_in[0];  // [S, B, D]
    const float* state = (const float*)d_in[1];  // [B, D]
    const float* W     = (const float*)d_in[2];  // [D, D]
    const float* bias  = (const float*)d_in[3];  // [D]
    float* out         = (float*)d_out;          // [B, S]

    stage1_part<<<dim3(DDIM / OTILE, KSPLIT), 128>>>(state, W);
    stage1_reduce<<<(BATCH * DDIM) / 256, 256>>>(bias);
    stage2_dots<<<dim3(S_LEN / 8, BATCH), 256>>>(enc, out);
}

// round 16
// speedup vs baseline: 1.1074x; 1.0078x over previous
#include <cuda_runtime.h>
#include <cuda_bf16.h>
#include <cstdint>

// Problem shapes (fixed by the dataset)
#define S_LEN 2048
#define BATCH 16
#define DDIM  2048

// Stage-1 tiling: O_t=2, B_t=16 per thread (R15 proven); 2 subtiles per block.
#define OTILE   256                 // o rows per block (2 per thread)
#define KSPLIT  32
#define KCHUNK  (DDIM / KSPLIT)     // 64 d per block, as 2 x 32-d subtiles
#define SUBK    32
#define NSUB    (KCHUNK / SUBK)     // 2
#define WPAD    33                  // sW bank = (r + d) % 32 -> conflict-free
#define SPAD    20                  // sS row stride (80B, 16B-aligned LDS.128)

// Scratch (device globals: allocation-free). g_part layout: [kc][o][b].
__device__ float g_part[KSPLIT * DDIM * BATCH];   // 4 MB
__device__ float g_altered[BATCH * DDIM];         // [b][o], 128 KB

__device__ __forceinline__ void ffma2(uint64_t& d, uint64_t a, uint64_t b) {
    asm("fma.rn.f32x2 %0, %1, %2, %0;" : "+l"(d) : "l"(a), "l"(b));
}

// ---------------------------------------------------------------------------
// Kernel 1a: partial[kc][o][b] = sum_{d in 64-chunk kc} state[b][d] * W[o][d]
// (identical to the 53.8us R15 version, plus a PDL trigger at the end)
// ---------------------------------------------------------------------------
__global__ void __launch_bounds__(128)
stage1_part(const float* __restrict__ state,
            const float* __restrict__ W)
{
    __shared__ float sW[OTILE][WPAD];   // 33.8 KB (reloaded per subtile)
    __shared__ float sS[SUBK][SPAD];    // 2.5 KB

    const int t     = threadIdx.x;      // 0..127
    const int obase = blockIdx.x * OTILE;
    const int kc    = blockIdx.y;

    uint64_t acc0[8], acc1[8];          // 2 o-rows x 8 b-pairs (f32x2)
#pragma unroll
    for (int i = 0; i < 8; ++i) { acc0[i] = 0ull; acc1[i] = 0ull; }

#pragma unroll
    for (int sc = 0; sc < NSUB; ++sc) {
        const int d0 = kc * KCHUNK + sc * SUBK;

        // Stage state subtile transposed: sS[d][b]. Coalesced float4 LDG.
        {
            const int b  = t >> 3;
            const int c4 = t & 7;
            const float4 v = *(const float4*)(state + b * DDIM + d0 + c4 * 4);
            sS[c4 * 4 + 0][b] = v.x;
            sS[c4 * 4 + 1][b] = v.y;
            sS[c4 * 4 + 2][b] = v.z;
            sS[c4 * 4 + 3][b] = v.w;
        }

        // Stage W tile 256 rows x 32 d: 2048 float4, 16/thread, coalesced.
#pragma unroll
        for (int j = 0; j < 16; ++j) {
            const int g  = j * 128 + t;
            const int r  = g >> 3;
            const int c4 = g & 7;
            const float4 v = *(const float4*)(W + (long)(obase + r) * DDIM + d0 + c4 * 4);
            sW[r][c4 * 4 + 0] = v.x;
            sW[r][c4 * 4 + 1] = v.y;
            sW[r][c4 * 4 + 2] = v.z;
            sW[r][c4 * 4 + 3] = v.w;
        }
        __syncthreads();

#pragma unroll 8
        for (int d = 0; d < SUBK; ++d) {
            const float w0 = sW[t][d];             // bank (t+d)%32
            const float w1 = sW[t + 128][d];
            uint64_t wp0, wp1;
            asm("mov.b64 %0, {%1, %1};" : "=l"(wp0) : "r"(__float_as_uint(w0)));
            asm("mov.b64 %0, {%1, %1};" : "=l"(wp1) : "r"(__float_as_uint(w1)));
            const ulonglong2 q0 = *(const ulonglong2*)&sS[d][0];   // broadcast
            const ulonglong2 q1 = *(const ulonglong2*)&sS[d][4];
            const ulonglong2 q2 = *(const ulonglong2*)&sS[d][8];
            const ulonglong2 q3 = *(const ulonglong2*)&sS[d][12];
            ffma2(acc0[0], wp0, q0.x);  ffma2(acc0[1], wp0, q0.y);
            ffma2(acc0[2], wp0, q1.x);  ffma2(acc0[3], wp0, q1.y);
            ffma2(acc0[4], wp0, q2.x);  ffma2(acc0[5], wp0, q2.y);
            ffma2(acc0[6], wp0, q3.x);  ffma2(acc0[7], wp0, q3.y);
            ffma2(acc1[0], wp1, q0.x);  ffma2(acc1[1], wp1, q0.y);
            ffma2(acc1[2], wp1, q1.x);  ffma2(acc1[3], wp1, q1.y);
            ffma2(acc1[4], wp1, q2.x);  ffma2(acc1[5], wp1, q2.y);
            ffma2(acc1[6], wp1, q3.x);  ffma2(acc1[7], wp1, q3.y);
        }
        __syncthreads();   // protect sW/sS before next subtile overwrite
    }

    // --- Store both partial rows: 16 consecutive floats each (4 STG.128).
#pragma unroll
    for (int half = 0; half < 2; ++half) {
        const uint64_t* a = half ? acc1 : acc0;
        float res[16];
#pragma unroll
        for (int j = 0; j < 8; ++j)
            asm("mov.b64 {%0, %1}, %2;"
                : "=f"(res[2 * j]), "=f"(res[2 * j + 1]) : "l"(a[j]));
        const int o = obase + t + 128 * half;
        float* dst = g_part + ((long)kc * DDIM + o) * BATCH;
#pragma unroll
        for (int q = 0; q < 4; ++q)
            *(float4*)(dst + q * 4) =
                make_float4(res[q * 4], res[q * 4 + 1], res[q * 4 + 2], res[q * 4 + 3]);
    }

#if __CUDA_ARCH__ >= 900
    cudaTriggerProgrammaticLaunchCompletion();
#endif
}

// ---------------------------------------------------------------------------
// Kernel 1b: altered[b][o] = bias[o] + sum_kc partial[kc][o][b]
// PDL dependent: launches during stage1_part's drain; does its setup, then
// gridDependencySynchronize before touching g_part.
// ---------------------------------------------------------------------------
__global__ void __launch_bounds__(256)
stage1_reduce(const float* __restrict__ bias)
{
    const int n = blockIdx.x * 256 + threadIdx.x;   // 0..32767
    const int o = n >> 4;
    const int b = n & 15;
    float v = bias[o];                               // independent of producer
#if __CUDA_ARCH__ >= 900
    cudaGridDependencySynchronize();
#endif
#pragma unroll
    for (int kc = 0; kc < KSPLIT; ++kc)
        v += __ldcg(&g_part[(long)kc * DDIM * BATCH + n]);
    g_altered[b * DDIM + o] = v;
#if __CUDA_ARCH__ >= 900
    cudaTriggerProgrammaticLaunchCompletion();
#endif
}

// ---------------------------------------------------------------------------
// Kernel 2: weights[b][s] = sum_d altered[b][d] * enc[s][b][d]
// PDL dependent: its 4096-CTA dispatch overlaps the reduce; each block does
// address setup, then gridDependencySynchronize before staging g_altered.
// ---------------------------------------------------------------------------
__global__ void __launch_bounds__(256, 8)
stage2_dots(const float* __restrict__ enc,
            float* __restrict__ out)
{
    __shared__ float alt[DDIM];

    const int tid    = threadIdx.x;
    const int warpId = tid >> 5;
    const int lane   = tid & 31;
    const int b      = blockIdx.y;
    const int s      = blockIdx.x * 8 + warpId;
    const float4* row = (const float4*)(enc + ((long)s * BATCH + b) * DDIM);

#if __CUDA_ARCH__ >= 900
    cudaGridDependencySynchronize();
#endif

#pragma unroll
    for (int j = 0; j < 2; ++j) {
        int f4 = tid + j * 256;
        *(float4*)&alt[f4 * 4] = *(const float4*)(g_altered + b * DDIM + f4 * 4);
    }
    __syncthreads();

    float4 acc = make_float4(0.f, 0.f, 0.f, 0.f);
#pragma unroll
    for (int i = 0; i < 16; ++i) {
        const int f4 = i * 32 + lane;
        const float4 e = __ldcs(row + f4);          // streaming load
        const float4 a = *(const float4*)&alt[f4 * 4];
        acc.x += e.x * a.x;
        acc.y += e.y * a.y;
        acc.z += e.z * a.z;
        acc.w += e.w * a.w;
    }

    float tt = (acc.x + acc.y) + (acc.z + acc.w);
#pragma unroll
    for (int off = 16; off > 0; off >>= 1)
        tt += __shfl_down_sync(0xFFFFFFFFu, tt, off);

    if (lane == 0)
        out[b * S_LEN + s] = tt;   // output shape [B, S]
}

// Helper: launch a kernel with the PDL (programmatic stream serialization)
// attribute on the default stream. Graph-capture legal.
template <typename... Args>
static void launch_pdl(void (*kern)(Args...), dim3 grid, dim3 block,
                       Args... args)
{
    cudaLaunchAttribute attr[1];
    attr[0].id = cudaLaunchAttributeProgrammaticStreamSerialization;
    attr[0].val.programmaticStreamSerializationAllowed = 1;
    cudaLaunchConfig_t cfg = {};
    cfg.gridDim  = grid;
    cfg.blockDim = block;
    cfg.stream   = 0;
    cfg.attrs    = attr;
    cfg.numAttrs = 1;
    cudaLaunchKernelEx(&cfg, kern, args...);
}

extern "C" void kernel_launch(void* const* d_in, const int* in_sizes, int n_in,
                              void* d_out, int out_size)
{
    const float* enc   = (const float*)d_in[0];  // [S, B, D]
    const float* state = (const float*)d_in[1];  // [B, D]
    const float* W     = (const float*)d_in[2];  // [D, D]
    const float* bias  = (const float*)d_in[3];  // [D]
    float* out         = (float*)d_out;          // [B, S]

    stage1_part<<<dim3(DDIM / OTILE, KSPLIT), 128>>>(state, W);
    launch_pdl(stage1_reduce, dim3((BATCH * DDIM) / 256), dim3(256), bias);
    launch_pdl(stage2_dots, dim3(S_LEN / 8, BATCH), dim3(256), enc, out);
}